// round 11
// baseline (speedup 1.0000x reference)
#include <cuda_runtime.h>
#include <cstdint>
#include <math.h>

// Problem constants (fixed by setup_inputs)
#define WINC    20
#define OFFSETC 40
#define FDIM    8192
#define CDIM    256
#define PDIM    256
#define SIL_BLOCKS 1024        // B * 32 chunks of 256 frames
#define PH_BLOCKS  1024        // B*P / 8 warps
#define NBLK    (SIL_BLOCKS + PH_BLOCKS)
#define NTHR    256

// Gaussian taps g[i] = exp(-0.5*((i-4)/4)^2) / sum, precomputed to float32
// accuracy (matches the jnp float32 computation to ~1e-7 relative).
#define G0 0.08167445f
#define G1 0.10164549f
#define G2 0.11883562f
#define G3 0.13051539f
#define G4 0.13465840f

__device__ __forceinline__ float block_reduce_sum(float v) {
    __shared__ float sh[8];
    int lane = threadIdx.x & 31;
    int w    = threadIdx.x >> 5;
    #pragma unroll
    for (int o = 16; o; o >>= 1) v += __shfl_down_sync(0xffffffffu, v, o);
    if (lane == 0) sh[w] = v;
    __syncthreads();
    if (w == 0) {
        v = (lane < 8) ? sh[lane] : 0.0f;
        #pragma unroll
        for (int o = 4; o; o >>= 1) v += __shfl_down_sync(0xffffffffu, v, o);
    }
    return v;
}

// 2048 blocks x 256 threads (R2's gather geometry — small barrier domains).
//  blocks [0, SIL_BLOCKS): silence, 256 frames each (b = bid>>5, ch = bid&31)
//  blocks [SIL_BLOCKS, NBLK): phonemes, one per warp (8 per block)
// Block partial -> RED.ADD.F32 into out[0] (all terms >= 0; reorder error ~1e-7).
__global__ void __launch_bounds__(NTHR)
fused_kernel(const float* __restrict__ X,
             const int* __restrict__ lengths,
             const int* __restrict__ tgt,
             const int* __restrict__ p_end,
             const int* __restrict__ pnum,
             float* __restrict__ out) {
    const unsigned FULL = 0xffffffffu;
    int bid  = blockIdx.x;
    int tid  = threadIdx.x;
    int lane = tid & 31;
    int wid  = tid >> 5;

    float contrib = 0.0f;

    if (bid < SIL_BLOCKS) {
        // ---------- silence term: one frame per thread ----------
        int b  = bid >> 5;                 // 32 chunks per batch
        int ch = bid & 31;
        int tf = (ch << 8) + tid;

        int len = __ldg(&lengths[b]);
        int pn  = __ldg(&pnum[b]);
        int ends_ph = min(__ldg(&p_end[b]) + OFFSETC, len);
        int first_start = max(ends_ph - WINC * pn, 0);
        int last_end    = min(max(ends_ph - WINC, 0) + WINC, len);

        // mask = (tf < first_start) | ((tf >= last_end) & (tf < len))
        if ((tf < first_start) || ((tf >= last_end) && (tf < len))) {
            contrib = -X[((size_t)b * FDIM + tf) * CDIM];   // SIL column = 0
        }
    } else {
        // ---------- phoneme term: one (b, p) per warp ----------
        int w = ((bid - SIL_BLOCKS) << 3) + wid;   // global warp id in [0, B*P)
        int b = w >> 8;                            // P = 256
        int p = w & 255;

        int len = __ldg(&lengths[b]);
        int pn  = __ldg(&pnum[b]);

        if (p < pn) {
            int ends_ph = min(__ldg(&p_end[b]) + OFFSETC, len);
            int start   = max(ends_ph - WINC * (pn - p), 0);
            int wlen    = min(start + WINC, len) - start;
            int c       = __ldg(&tgt[b * PDIM + p]);

            float v = 0.0f;
            if (lane < WINC && lane < wlen) {
                int fi = min(start + lane, FDIM - 1);
                v = X[((size_t)b * FDIM + fi) * CDIM + c];
            }

            // smoothed[lane] = sum_i g[i] * v[lane + i - 3]; out-of-range -> 0
            // (idx & 31 wraps onto lanes >= 20 which hold v = 0)
            float v0 = __shfl_sync(FULL, v, (lane - 3) & 31);
            float v1 = __shfl_sync(FULL, v, (lane - 2) & 31);
            float v2 = __shfl_sync(FULL, v, (lane - 1) & 31);
            float v4 = __shfl_sync(FULL, v, (lane + 1) & 31);
            float v5 = __shfl_sync(FULL, v, (lane + 2) & 31);
            float v6 = __shfl_sync(FULL, v, (lane + 3) & 31);
            float v7 = __shfl_sync(FULL, v, (lane + 4) & 31);
            float v8 = __shfl_sync(FULL, v, (lane + 5) & 31);
            float sm = G0 * v0;
            sm = fmaf(G1, v1, sm);
            sm = fmaf(G2, v2, sm);
            sm = fmaf(G3, v,  sm);
            sm = fmaf(G4, v4, sm);
            sm = fmaf(G3, v5, sm);
            sm = fmaf(G2, v6, sm);
            sm = fmaf(G1, v7, sm);
            sm = fmaf(G0, v8, sm);

            float m = (lane < wlen && lane < WINC) ? sm : -INFINITY;
            #pragma unroll
            for (int o = 16; o; o >>= 1) m = fmaxf(m, __shfl_xor_sync(FULL, m, o));
            if (lane == 0) contrib = -m;
        }
    }

    float tot = block_reduce_sum(contrib);
    if (tid == 0) atomicAdd(out, tot);     // RED.ADD.F32, no-return fast path
}

extern "C" void kernel_launch(void* const* d_in, const int* in_sizes, int n_in,
                              void* d_out, int out_size) {
    const float* X       = (const float*)d_in[0];
    const int*   lengths = (const int*)d_in[1];
    const int*   tgt     = (const int*)d_in[2];
    const int*   p_end   = (const int*)d_in[3];
    const int*   pnum    = (const int*)d_in[4];
    float*       out     = (float*)d_out;

    cudaMemsetAsync(out, 0, sizeof(float));          // graph-capturable memset node
    fused_kernel<<<NBLK, NTHR>>>(X, lengths, tgt, p_end, pnum, out);
}

// round 12
// speedup vs baseline: 1.0126x; 1.0126x over previous
#include <cuda_runtime.h>
#include <cstdint>
#include <math.h>

// Problem constants (fixed by setup_inputs)
#define WINC    20
#define OFFSETC 40
#define FDIM    8192
#define CDIM    256
#define PDIM    256
#define SIL_BLOCKS 512         // 512 frames per block (2 per thread), B*F total
#define PH_BLOCKS  512         // 16 phonemes per block (2 per warp), B*P total
#define NBLK    (SIL_BLOCKS + PH_BLOCKS)   // 1024 -> single wave (8 blk/SM x 148)
#define NTHR    256

// Gaussian taps g[i] = exp(-0.5*((i-4)/4)^2) / sum, precomputed to float32
// accuracy (matches the jnp float32 computation to ~1e-7 relative).
#define G0 0.08167445f
#define G1 0.10164549f
#define G2 0.11883562f
#define G3 0.13051539f
#define G4 0.13465840f

__device__ __forceinline__ float block_reduce_sum(float v) {
    __shared__ float sh[8];
    int lane = threadIdx.x & 31;
    int w    = threadIdx.x >> 5;
    #pragma unroll
    for (int o = 16; o; o >>= 1) v += __shfl_down_sync(0xffffffffu, v, o);
    if (lane == 0) sh[w] = v;
    __syncthreads();
    if (w == 0) {
        v = (lane < 8) ? sh[lane] : 0.0f;
        #pragma unroll
        for (int o = 4; o; o >>= 1) v += __shfl_down_sync(0xffffffffu, v, o);
    }
    return v;
}

// Per-warp phoneme evaluation from a gathered lane value.
__device__ __forceinline__ float phoneme_eval(float v, int wlen, int lane) {
    const unsigned FULL = 0xffffffffu;
    float v0 = __shfl_sync(FULL, v, (lane - 3) & 31);
    float v1 = __shfl_sync(FULL, v, (lane - 2) & 31);
    float v2 = __shfl_sync(FULL, v, (lane - 1) & 31);
    float v4 = __shfl_sync(FULL, v, (lane + 1) & 31);
    float v5 = __shfl_sync(FULL, v, (lane + 2) & 31);
    float v6 = __shfl_sync(FULL, v, (lane + 3) & 31);
    float v7 = __shfl_sync(FULL, v, (lane + 4) & 31);
    float v8 = __shfl_sync(FULL, v, (lane + 5) & 31);
    float sm = G0 * v0;
    sm = fmaf(G1, v1, sm);
    sm = fmaf(G2, v2, sm);
    sm = fmaf(G3, v,  sm);
    sm = fmaf(G4, v4, sm);
    sm = fmaf(G3, v5, sm);
    sm = fmaf(G2, v6, sm);
    sm = fmaf(G1, v7, sm);
    sm = fmaf(G0, v8, sm);
    float m = (lane < wlen && lane < WINC) ? sm : -INFINITY;
    #pragma unroll
    for (int o = 16; o; o >>= 1) m = fmaxf(m, __shfl_xor_sync(FULL, m, o));
    return (lane == 0) ? -m : 0.0f;
}

// Single-wave kernel: 1024 blocks x 256 threads.
//  blocks [0, SIL_BLOCKS): silence, 512 frames each (2 per thread, MLP=2)
//  blocks [SIL_BLOCKS, NBLK): phonemes, 16 each (2 per warp, both gathers
//  front-batched before either conv).
// Block partial -> RED.ADD.F32 into out[0] (all terms >= 0; reorder ~1e-7).
__global__ void __launch_bounds__(NTHR)
fused_kernel(const float* __restrict__ X,
             const int* __restrict__ lengths,
             const int* __restrict__ tgt,
             const int* __restrict__ p_end,
             const int* __restrict__ pnum,
             float* __restrict__ out) {
    int bid  = blockIdx.x;
    int tid  = threadIdx.x;
    int lane = tid & 31;
    int wid  = tid >> 5;

    float contrib = 0.0f;

    if (bid < SIL_BLOCKS) {
        // ---------- silence term: 2 independent frames per thread ----------
        int b  = bid >> 4;                 // 16 chunks of 512 frames per batch
        int ch = bid & 15;

        int len = __ldg(&lengths[b]);
        int pn  = __ldg(&pnum[b]);
        int ends_ph = min(__ldg(&p_end[b]) + OFFSETC, len);
        int first_start = max(ends_ph - WINC * pn, 0);
        int last_end    = min(max(ends_ph - WINC, 0) + WINC, len);

        int tf1 = (ch << 9) + tid;
        int tf2 = tf1 + 256;
        const float* xp = X + (size_t)b * FDIM * CDIM;

        bool m1 = (tf1 < first_start) || ((tf1 >= last_end) && (tf1 < len));
        bool m2 = (tf2 < first_start) || ((tf2 >= last_end) && (tf2 < len));
        float s1 = 0.0f, s2 = 0.0f;
        if (m1) s1 = xp[(size_t)tf1 * CDIM];   // SIL column = 0
        if (m2) s2 = xp[(size_t)tf2 * CDIM];
        contrib = -s1 - s2;
    } else {
        // ---------- phoneme term: 2 phonemes per warp ----------
        int w  = ((bid - SIL_BLOCKS) << 3) + wid;  // [0, B*P/2)
        int b  = w >> 7;                           // 128 warp-slots per batch
        int p1 = (w & 127) << 1;                   // even phoneme
        int p2 = p1 + 1;

        int len = __ldg(&lengths[b]);
        int pn  = __ldg(&pnum[b]);
        int ends_ph = min(__ldg(&p_end[b]) + OFFSETC, len);
        const float* xp = X + (size_t)b * FDIM * CDIM;

        int start1 = max(ends_ph - WINC * (pn - p1), 0);
        int start2 = max(ends_ph - WINC * (pn - p2), 0);
        int wlen1  = min(start1 + WINC, len) - start1;
        int wlen2  = min(start2 + WINC, len) - start2;
        int c1 = __ldg(&tgt[b * PDIM + p1]);
        int c2 = __ldg(&tgt[b * PDIM + p2]);

        // front-batch both 20-lane gathers
        float v1 = 0.0f, v2 = 0.0f;
        bool a1 = (p1 < pn) && (lane < WINC) && (lane < wlen1);
        bool a2 = (p2 < pn) && (lane < WINC) && (lane < wlen2);
        if (a1) v1 = xp[(size_t)min(start1 + lane, FDIM - 1) * CDIM + c1];
        if (a2) v2 = xp[(size_t)min(start2 + lane, FDIM - 1) * CDIM + c2];

        if (p1 < pn) contrib += phoneme_eval(v1, wlen1, lane);
        if (p2 < pn) contrib += phoneme_eval(v2, wlen2, lane);
    }

    float tot = block_reduce_sum(contrib);
    if (tid == 0) atomicAdd(out, tot);     // RED.ADD.F32, no-return fast path
}

extern "C" void kernel_launch(void* const* d_in, const int* in_sizes, int n_in,
                              void* d_out, int out_size) {
    const float* X       = (const float*)d_in[0];
    const int*   lengths = (const int*)d_in[1];
    const int*   tgt     = (const int*)d_in[2];
    const int*   p_end   = (const int*)d_in[3];
    const int*   pnum    = (const int*)d_in[4];
    float*       out     = (float*)d_out;

    cudaMemsetAsync(out, 0, sizeof(float));          // graph-capturable memset node
    fused_kernel<<<NBLK, NTHR>>>(X, lengths, tgt, p_end, pnum, out);
}